// round 1
// baseline (speedup 1.0000x reference)
#include <cuda_runtime.h>
#include <math.h>

// Problem constants
#define BB   8
#define SS   1024
#define DD   1024
#define HH   16
#define HD   64
#define MROWS (BB*SS)   // 8192

// Scratch (allocation-free rule: __device__ globals)
__device__ float g_q[MROWS*DD];    // [B,H,S,HD]
__device__ float g_k[MROWS*DD];
__device__ float g_v[MROWS*DD];
__device__ float g_att[MROWS*DD];  // [B,S,D]

// ---------------------------------------------------------------------------
// SGEMM: C[M,N] = A[M,K] * W[N,K]^T + bias[N]
// M=8192, N=1024, K=1024. 128x128 tile, BK=8, 256 threads, 8x8 per thread.
// split_heads=1 writes C into [B,H,S,HD] layout; else row-major [M,N].
// ---------------------------------------------------------------------------
__global__ __launch_bounds__(256) void sgemm_bias(
    const float* __restrict__ A, const float* __restrict__ W,
    const float* __restrict__ bias, float* __restrict__ out, int split_heads)
{
    __shared__ float As[8][128];
    __shared__ float Bs[8][128];

    const int tid = threadIdx.x;
    const int bm  = blockIdx.y << 7;
    const int bn  = blockIdx.x << 7;

    const int lr = tid >> 1;          // 0..127 (tile row for loads)
    const int lk = (tid & 1) << 2;    // 0 or 4  (k offset for loads)
    const float* Ap = A + (size_t)(bm + lr) * DD + lk;
    const float* Wp = W + (size_t)(bn + lr) * DD + lk;

    const int tr = (tid >> 4) << 3;   // thread row base in tile
    const int tc = (tid & 15) << 3;   // thread col base in tile

    float acc[8][8];
    #pragma unroll
    for (int i = 0; i < 8; i++)
        #pragma unroll
        for (int j = 0; j < 8; j++) acc[i][j] = 0.f;

    for (int k0 = 0; k0 < DD; k0 += 8) {
        float4 av = *(const float4*)(Ap + k0);
        float4 wv = *(const float4*)(Wp + k0);
        __syncthreads();   // previous iteration's compute done before overwrite
        As[lk+0][lr] = av.x; As[lk+1][lr] = av.y;
        As[lk+2][lr] = av.z; As[lk+3][lr] = av.w;
        Bs[lk+0][lr] = wv.x; Bs[lk+1][lr] = wv.y;
        Bs[lk+2][lr] = wv.z; Bs[lk+3][lr] = wv.w;
        __syncthreads();

        #pragma unroll
        for (int kk = 0; kk < 8; kk++) {
            float a[8], b[8];
            *(float4*)&a[0] = *(const float4*)&As[kk][tr];
            *(float4*)&a[4] = *(const float4*)&As[kk][tr+4];
            *(float4*)&b[0] = *(const float4*)&Bs[kk][tc];
            *(float4*)&b[4] = *(const float4*)&Bs[kk][tc+4];
            #pragma unroll
            for (int i = 0; i < 8; i++)
                #pragma unroll
                for (int j = 0; j < 8; j++)
                    acc[i][j] = fmaf(a[i], b[j], acc[i][j]);
        }
    }

    #pragma unroll
    for (int i = 0; i < 8; i++) {
        const int m = bm + tr + i;
        #pragma unroll
        for (int j0 = 0; j0 < 8; j0 += 4) {
            const int n = bn + tc + j0;
            float4 r;
            r.x = acc[i][j0+0] + bias[n+0];
            r.y = acc[i][j0+1] + bias[n+1];
            r.z = acc[i][j0+2] + bias[n+2];
            r.w = acc[i][j0+3] + bias[n+3];
            size_t idx;
            if (split_heads) {
                const int b_ = m >> 10, s_ = m & 1023;
                const int h_ = n >> 6,  d_ = n & 63;
                idx = ((size_t)(b_*HH + h_)*SS + s_)*HD + d_;
            } else {
                idx = (size_t)m * DD + n;
            }
            *(float4*)(out + idx) = r;
        }
    }
}

// ---------------------------------------------------------------------------
// Flash attention (fp32): one block = 64 query rows of one (b,h).
// grid (S/64, H, B), 256 threads (16x16), each thread owns 4x4 of every tile.
// Online softmax; causal + key-pad (input_ids==1) masking.
// smem (dynamic 64KB): Qt[d][r], Kt[d][c], Vs[k][d], Pt[k][r]  (all 64x64)
// ---------------------------------------------------------------------------
__global__ __launch_bounds__(256) void flash_attn(const long long* __restrict__ ids)
{
    extern __shared__ float sm[];
    float* Qt = sm;            // transposed: Qt[d*64 + qrow], pre-scaled by 1/8
    float* Kt = sm + 4096;     // transposed: Kt[d*64 + krow]
    float* Vs = sm + 8192;     // natural:    Vs[k*64 + d]
    float* Pt = sm + 12288;    // transposed: Pt[k*64 + qrow]
    __shared__ int kval[64];

    const int tid = threadIdx.x;
    const int ty  = tid >> 4;
    const int tx  = tid & 15;
    const int qt  = blockIdx.x;
    const int h   = blockIdx.y;
    const int b   = blockIdx.z;
    const size_t headoff = (size_t)(b*HH + h) * SS * HD;

    // Load Q tile transposed, folding in 1/sqrt(HD)=0.125
    {
        const float* qbase = g_q + headoff + (size_t)qt * 64 * HD;
        #pragma unroll
        for (int v = 0; v < 4; v++) {
            const int idx = v*1024 + tid*4;
            const int r = idx >> 6, d = idx & 63;
            float4 qv = *(const float4*)(qbase + idx);
            Qt[(d+0)*64 + r] = qv.x * 0.125f;
            Qt[(d+1)*64 + r] = qv.y * 0.125f;
            Qt[(d+2)*64 + r] = qv.z * 0.125f;
            Qt[(d+3)*64 + r] = qv.w * 0.125f;
        }
    }

    float acc[4][4];
    #pragma unroll
    for (int i = 0; i < 4; i++)
        #pragma unroll
        for (int j = 0; j < 4; j++) acc[i][j] = 0.f;
    float mrow[4] = {-INFINITY, -INFINITY, -INFINITY, -INFINITY};
    float lrow[4] = {0.f, 0.f, 0.f, 0.f};

    for (int kt = 0; kt <= qt; kt++) {
        __syncthreads();   // protect Kt/Vs from previous iteration's readers
        const float* kbase = g_k + headoff + (size_t)kt * 4096;
        const float* vbase = g_v + headoff + (size_t)kt * 4096;
        #pragma unroll
        for (int v = 0; v < 4; v++) {
            const int idx = v*1024 + tid*4;
            const int r = idx >> 6, d = idx & 63;
            float4 kv = *(const float4*)(kbase + idx);
            Kt[(d+0)*64 + r] = kv.x;
            Kt[(d+1)*64 + r] = kv.y;
            Kt[(d+2)*64 + r] = kv.z;
            Kt[(d+3)*64 + r] = kv.w;
            *(float4*)(Vs + idx) = *(const float4*)(vbase + idx);
        }
        if (tid < 64)
            kval[tid] = (ids[(size_t)b*SS + kt*64 + tid] != 1LL) ? 1 : 0;
        __syncthreads();

        // S = (Q/8) . K^T  (64x64x64 rank-1 updates)
        float s[4][4];
        #pragma unroll
        for (int i = 0; i < 4; i++)
            #pragma unroll
            for (int j = 0; j < 4; j++) s[i][j] = 0.f;
        #pragma unroll 8
        for (int k = 0; k < 64; k++) {
            float4 a  = *(const float4*)(Qt + k*64 + ty*4);
            float4 bb = *(const float4*)(Kt + k*64 + tx*4);
            const float av[4] = {a.x, a.y, a.z, a.w};
            const float bv[4] = {bb.x, bb.y, bb.z, bb.w};
            #pragma unroll
            for (int i = 0; i < 4; i++)
                #pragma unroll
                for (int j = 0; j < 4; j++)
                    s[i][j] = fmaf(av[i], bv[j], s[i][j]);
        }

        // Masking: causal (key > query) and pad keys
        #pragma unroll
        for (int j = 0; j < 4; j++) {
            const int kc = tx*4 + j;
            const bool vj = (kval[kc] != 0);
            const int kglob = kt*64 + kc;
            #pragma unroll
            for (int i = 0; i < 4; i++) {
                const int qglob = qt*64 + ty*4 + i;
                if (!vj || kglob > qglob) s[i][j] = -INFINITY;
            }
        }

        // Online softmax update per row (row group = 16 lanes sharing ty)
        #pragma unroll
        for (int i = 0; i < 4; i++) {
            float rm = fmaxf(fmaxf(s[i][0], s[i][1]), fmaxf(s[i][2], s[i][3]));
            #pragma unroll
            for (int o = 8; o > 0; o >>= 1)
                rm = fmaxf(rm, __shfl_xor_sync(0xffffffffu, rm, o));
            const float mnew = fmaxf(mrow[i], rm);
            const float alpha = (mrow[i] == -INFINITY) ? 0.f : __expf(mrow[i] - mnew);
            float p[4], ps = 0.f;
            #pragma unroll
            for (int j = 0; j < 4; j++) {
                p[j] = (s[i][j] == -INFINITY) ? 0.f : __expf(s[i][j] - mnew);
                ps += p[j];
            }
            #pragma unroll
            for (int o = 8; o > 0; o >>= 1)
                ps += __shfl_xor_sync(0xffffffffu, ps, o);
            lrow[i] = lrow[i] * alpha + ps;
            mrow[i] = mnew;
            #pragma unroll
            for (int j = 0; j < 4; j++) {
                acc[i][j] *= alpha;
                Pt[(tx*4 + j)*64 + ty*4 + i] = p[j];
            }
        }
        __syncwarp();  // Pt writers/readers share the same 16-lane ty-group

        // O += P . V
        #pragma unroll 8
        for (int k = 0; k < 64; k++) {
            float4 pv = *(const float4*)(Pt + k*64 + ty*4);
            float4 vv = *(const float4*)(Vs + k*64 + tx*4);
            const float pa[4] = {pv.x, pv.y, pv.z, pv.w};
            const float vb[4] = {vv.x, vv.y, vv.z, vv.w};
            #pragma unroll
            for (int i = 0; i < 4; i++)
                #pragma unroll
                for (int j = 0; j < 4; j++)
                    acc[i][j] = fmaf(pa[i], vb[j], acc[i][j]);
        }
    }

    // Epilogue: normalize and write [B,S,D]
    #pragma unroll
    for (int i = 0; i < 4; i++) {
        const float rinv = (lrow[i] > 0.f) ? 1.f / lrow[i] : 0.f;
        const int qr = qt*64 + ty*4 + i;
        float4 o;
        o.x = acc[i][0] * rinv;
        o.y = acc[i][1] * rinv;
        o.z = acc[i][2] * rinv;
        o.w = acc[i][3] * rinv;
        *(float4*)(g_att + ((size_t)b*SS + qr)*DD + h*HD + tx*4) = o;
    }
}

// ---------------------------------------------------------------------------
extern "C" void kernel_launch(void* const* d_in, const int* in_sizes, int n_in,
                              void* d_out, int out_size)
{
    const float*     x   = (const float*)d_in[0];
    const long long* ids = (const long long*)d_in[1];
    const float*     Wq  = (const float*)d_in[2];
    const float*     bq  = (const float*)d_in[3];
    const float*     Wk  = (const float*)d_in[4];
    const float*     bk  = (const float*)d_in[5];
    const float*     Wv  = (const float*)d_in[6];
    const float*     bv  = (const float*)d_in[7];
    const float*     Wo  = (const float*)d_in[8];
    const float*     bo  = (const float*)d_in[9];
    float* out = (float*)d_out;

    float *q, *k, *v, *att;
    cudaGetSymbolAddress((void**)&q,   g_q);
    cudaGetSymbolAddress((void**)&k,   g_k);
    cudaGetSymbolAddress((void**)&v,   g_v);
    cudaGetSymbolAddress((void**)&att, g_att);

    const dim3 gg(DD/128, MROWS/128);   // (8, 64)

    sgemm_bias<<<gg, 256>>>(x, Wq, bq, q, 1);
    sgemm_bias<<<gg, 256>>>(x, Wk, bk, k, 1);
    sgemm_bias<<<gg, 256>>>(x, Wv, bv, v, 1);

    cudaFuncSetAttribute(flash_attn,
                         cudaFuncAttributeMaxDynamicSharedMemorySize, 65536);
    flash_attn<<<dim3(SS/64, HH, BB), 256, 65536>>>(ids);

    sgemm_bias<<<gg, 256>>>(att, Wo, bo, out, 0);
}

// round 3
// speedup vs baseline: 1.7617x; 1.7617x over previous
#include <cuda_runtime.h>
#include <cuda_bf16.h>
#include <math.h>
#include <stdint.h>

// Problem constants
#define BB   8
#define SS   1024
#define DD   1024
#define HH   16
#define HD   64
#define MROWS (BB*SS)   // 8192
#define NCHUNK 32       // K / 32
#define STAGES 4

// Scratch (allocation-free rule: __device__ globals)
__device__ float g_q[MROWS*DD];    // [B,H,S,HD]
__device__ float g_k[MROWS*DD];
__device__ float g_v[MROWS*DD];
__device__ float g_att[MROWS*DD];  // [B,S,D]

// Packed bf16 hi/lo operands: layout [row][kchunk(32)][hi 32 bf16 | lo 32 bf16]
__device__ __nv_bfloat16 g_xc [MROWS*2048];
__device__ __nv_bfloat16 g_ac [MROWS*2048];
__device__ __nv_bfloat16 g_wqc[DD*2048];
__device__ __nv_bfloat16 g_wkc[DD*2048];
__device__ __nv_bfloat16 g_wvc[DD*2048];
__device__ __nv_bfloat16 g_woc[DD*2048];

// ---------------------------------------------------------------------------
// PTX helpers
// ---------------------------------------------------------------------------
__device__ __forceinline__ uint32_t smem_u32(const void* p) {
    uint32_t a;
    asm("{ .reg .u64 t; cvta.to.shared.u64 t, %1; cvt.u32.u64 %0, t; }" : "=r"(a) : "l"(p));
    return a;
}
__device__ __forceinline__ void cp16(uint32_t dst, const void* src) {
    asm volatile("cp.async.cg.shared.global [%0], [%1], 16;" :: "r"(dst), "l"(src));
}
#define CP_COMMIT() asm volatile("cp.async.commit_group;" ::: "memory")
#define CP_WAIT(n)  asm volatile("cp.async.wait_group %0;" :: "n"(n) : "memory")

__device__ __forceinline__ void ldsm4(uint32_t* r, uint32_t addr) {
    asm volatile("ldmatrix.sync.aligned.m8n8.x4.shared.b16 {%0,%1,%2,%3}, [%4];"
                 : "=r"(r[0]), "=r"(r[1]), "=r"(r[2]), "=r"(r[3]) : "r"(addr));
}
__device__ __forceinline__ void mma_bf16(float* d, const uint32_t* a, const uint32_t* b) {
    asm volatile("mma.sync.aligned.m16n8k16.row.col.f32.bf16.bf16.f32 "
                 "{%0,%1,%2,%3}, {%4,%5,%6,%7}, {%8,%9}, {%0,%1,%2,%3};"
                 : "+f"(d[0]), "+f"(d[1]), "+f"(d[2]), "+f"(d[3])
                 : "r"(a[0]), "r"(a[1]), "r"(a[2]), "r"(a[3]), "r"(b[0]), "r"(b[1]));
}

// ---------------------------------------------------------------------------
// Split-convert: fp32 [rows][1024] -> packed bf16 [rows][32][hi32|lo32]
// One thread handles 8 consecutive elements. rows*128 threads total.
// ---------------------------------------------------------------------------
__global__ __launch_bounds__(256) void convert_split(
    const float* __restrict__ in, __nv_bfloat16* __restrict__ out, int rows)
{
    const int g = blockIdx.x * 256 + threadIdx.x;
    if (g >= rows * 128) return;
    const int row  = g >> 7;
    const int w    = g & 127;
    const int kc   = w >> 2;
    const int part = w & 3;

    const float* src = in + (size_t)row * 1024 + kc * 32 + part * 8;
    float4 f0 = *(const float4*)(src);
    float4 f1 = *(const float4*)(src + 4);
    const float xs[8] = {f0.x, f0.y, f0.z, f0.w, f1.x, f1.y, f1.z, f1.w};

    alignas(16) __nv_bfloat16 h[8];
    alignas(16) __nv_bfloat16 l[8];
    #pragma unroll
    for (int e = 0; e < 8; e++) {
        h[e] = __float2bfloat16_rn(xs[e]);
        l[e] = __float2bfloat16_rn(xs[e] - __bfloat162float(h[e]));
    }
    __nv_bfloat16* dst = out + ((size_t)row * 32 + kc) * 64 + part * 8;
    *(uint4*)(dst)      = *(const uint4*)h;
    *(uint4*)(dst + 32) = *(const uint4*)l;
}

// ---------------------------------------------------------------------------
// bf16 3-term split GEMM via mma.sync: C[M,N] = A[M,K] * W[N,K]^T + bias[N]
// A, W pre-packed as [row][32][hi32|lo32] bf16. M=8192, N=1024, K=1024.
// CTA: 128x128 tile, 256 threads (8 warps, 4x2), 4-stage cp.async pipeline.
// smem per stage: A 16KB + B 16KB (128 rows x 128B, XOR-swizzled 16B chunks).
// ---------------------------------------------------------------------------
__global__ __launch_bounds__(256) void gemm_bf16(
    const __nv_bfloat16* __restrict__ Ap, const __nv_bfloat16* __restrict__ Bp,
    const float* __restrict__ bias, float* __restrict__ out, int split_heads)
{
    extern __shared__ char dsm[];
    const uint32_t smem_base = smem_u32(dsm);

    const int tid  = threadIdx.x;
    const int wid  = tid >> 5;
    const int lane = tid & 31;
    const int bm   = blockIdx.y << 7;
    const int bn   = blockIdx.x << 7;

    const int wm = (wid & 3) << 5;   // warp M offset (0,32,64,96)
    const int wn = (wid >> 2) << 6;  // warp N offset (0,64)

    // ---- async tile loader: chunk kc -> stage s
    auto load_stage = [&](int kc, int s) {
        const uint32_t sA = smem_base + s * 32768;
        const uint32_t sB = sA + 16384;
        #pragma unroll
        for (int v = 0; v < 4; v++) {
            const int cid = v * 256 + tid;      // 0..1023
            const int row = cid >> 3;
            const int c   = cid & 7;
            const uint32_t so = row * 128 + ((c ^ (row & 7)) << 4);
            cp16(sA + so, Ap + (((size_t)(bm + row) * 32 + kc) << 6) + c * 8);
            cp16(sB + so, Bp + (((size_t)(bn + row) * 32 + kc) << 6) + c * 8);
        }
        CP_COMMIT();
    };

    float acc[2][8][4];
    #pragma unroll
    for (int i = 0; i < 2; i++)
        #pragma unroll
        for (int j = 0; j < 8; j++)
            #pragma unroll
            for (int e = 0; e < 4; e++) acc[i][j][e] = 0.f;

    // prologue: stages 0..2 <- chunks 0..2
    load_stage(0, 0);
    load_stage(1, 1);
    load_stage(2, 2);

    for (int i = 0; i < NCHUNK; i++) {
        CP_WAIT(2);
        __syncthreads();

        const int s = i & (STAGES - 1);
        const uint32_t sA = smem_base + s * 32768;
        const uint32_t sB = sA + 16384;

        #pragma unroll
        for (int ks = 0; ks < 2; ks++) {
            uint32_t Ah[2][4], Al[2][4], Bh[8][2], Bl[8][2];
            const int chi = ks * 2 + (lane >> 4);
            const int clo = chi + 4;

            #pragma unroll
            for (int f = 0; f < 2; f++) {
                const int r = wm + f * 16 + (lane & 15);
                const uint32_t rb = sA + r * 128;
                ldsm4(Ah[f], rb + ((chi ^ (r & 7)) << 4));
                ldsm4(Al[f], rb + ((clo ^ (r & 7)) << 4));
            }
            #pragma unroll
            for (int p = 0; p < 4; p++) {
                const int r = wn + p * 16 + (lane & 15);
                const uint32_t rb = sB + r * 128;
                uint32_t q[4];
                ldsm4(q, rb + ((chi ^ (r & 7)) << 4));
                Bh[2*p][0] = q[0]; Bh[2*p][1] = q[2];
                Bh[2*p+1][0] = q[1]; Bh[2*p+1][1] = q[3];
                ldsm4(q, rb + ((clo ^ (r & 7)) << 4));
                Bl[2*p][0] = q[0]; Bl[2*p][1] = q[2];
                Bl[2*p+1][0] = q[1]; Bl[2*p+1][1] = q[3];
            }

            #pragma unroll
            for (int f = 0; f < 2; f++)
                #pragma unroll
                for (int j = 0; j < 8; j++) {
                    mma_bf16(acc[f][j], Ah[f], Bh[j]);
                    mma_bf16(acc[f][j], Ah[f], Bl[j]);
                    mma_bf16(acc[f][j], Al[f], Bh[j]);
                }
        }

        __syncthreads();
        if (i + STAGES - 1 < NCHUNK)
            load_stage(i + STAGES - 1, (i + STAGES - 1) & (STAGES - 1));
    }

    // ---- epilogue: acc -> out (+bias)
    #pragma unroll
    for (int f = 0; f < 2; f++) {
        #pragma unroll
        for (int j = 0; j < 8; j++) {
            const int col = bn + wn + j * 8 + ((lane & 3) << 1);
            const float b0 = bias[col], b1 = bias[col + 1];
            #pragma unroll
            for (int half = 0; half < 2; half++) {
                const int m = bm + wm + f * 16 + (lane >> 2) + half * 8;
                float2 o;
                o.x = acc[f][j][half * 2 + 0] + b0;
                o.y = acc[f][j][half * 2 + 1] + b1;
                size_t idx;
                if (split_heads) {
                    const int b_ = m >> 10, s_ = m & 1023;
                    const int h_ = col >> 6, d_ = col & 63;
                    idx = ((size_t)(b_ * HH + h_) * SS + s_) * HD + d_;
                } else {
                    idx = (size_t)m * DD + col;
                }
                *(float2*)(out + idx) = o;
            }
        }
    }
}

// ---------------------------------------------------------------------------
// Flash attention (fp32) — unchanged (round-4 target)
// ---------------------------------------------------------------------------
__global__ __launch_bounds__(256) void flash_attn(const long long* __restrict__ ids)
{
    extern __shared__ float sm[];
    float* Qt = sm;
    float* Kt = sm + 4096;
    float* Vs = sm + 8192;
    float* Pt = sm + 12288;
    __shared__ int kval[64];

    const int tid = threadIdx.x;
    const int ty  = tid >> 4;
    const int tx  = tid & 15;
    const int qt  = blockIdx.x;
    const int h   = blockIdx.y;
    const int b   = blockIdx.z;
    const size_t headoff = (size_t)(b*HH + h) * SS * HD;

    {
        const float* qbase = g_q + headoff + (size_t)qt * 64 * HD;
        #pragma unroll
        for (int v = 0; v < 4; v++) {
            const int idx = v*1024 + tid*4;
            const int r = idx >> 6, d = idx & 63;
            float4 qv = *(const float4*)(qbase + idx);
            Qt[(d+0)*64 + r] = qv.x * 0.125f;
            Qt[(d+1)*64 + r] = qv.y * 0.125f;
            Qt[(d+2)*64 + r] = qv.z * 0.125f;
            Qt[(d+3)*64 + r] = qv.w * 0.125f;
        }
    }

    float acc[4][4];
    #pragma unroll
    for (int i = 0; i < 4; i++)
        #pragma unroll
        for (int j = 0; j < 4; j++) acc[i][j] = 0.f;
    float mrow[4] = {-INFINITY, -INFINITY, -INFINITY, -INFINITY};
    float lrow[4] = {0.f, 0.f, 0.f, 0.f};

    for (int kt = 0; kt <= qt; kt++) {
        __syncthreads();
        const float* kbase = g_k + headoff + (size_t)kt * 4096;
        const float* vbase = g_v + headoff + (size_t)kt * 4096;
        #pragma unroll
        for (int v = 0; v < 4; v++) {
            const int idx = v*1024 + tid*4;
            const int r = idx >> 6, d = idx & 63;
            float4 kv = *(const float4*)(kbase + idx);
            Kt[(d+0)*64 + r] = kv.x;
            Kt[(d+1)*64 + r] = kv.y;
            Kt[(d+2)*64 + r] = kv.z;
            Kt[(d+3)*64 + r] = kv.w;
            *(float4*)(Vs + idx) = *(const float4*)(vbase + idx);
        }
        if (tid < 64)
            kval[tid] = (ids[(size_t)b*SS + kt*64 + tid] != 1LL) ? 1 : 0;
        __syncthreads();

        float s[4][4];
        #pragma unroll
        for (int i = 0; i < 4; i++)
            #pragma unroll
            for (int j = 0; j < 4; j++) s[i][j] = 0.f;
        #pragma unroll 8
        for (int k = 0; k < 64; k++) {
            float4 a  = *(const float4*)(Qt + k*64 + ty*4);
            float4 bb = *(const float4*)(Kt + k*64 + tx*4);
            const float av[4] = {a.x, a.y, a.z, a.w};
            const float bv[4] = {bb.x, bb.y, bb.z, bb.w};
            #pragma unroll
            for (int i = 0; i < 4; i++)
                #pragma unroll
                for (int j = 0; j < 4; j++)
                    s[i][j] = fmaf(av[i], bv[j], s[i][j]);
        }

        #pragma unroll
        for (int j = 0; j < 4; j++) {
            const int kc = tx*4 + j;
            const bool vj = (kval[kc] != 0);
            const int kglob = kt*64 + kc;
            #pragma unroll
            for (int i = 0; i < 4; i++) {
                const int qglob = qt*64 + ty*4 + i;
                if (!vj || kglob > qglob) s[i][j] = -INFINITY;
            }
        }

        #pragma unroll
        for (int i = 0; i < 4; i++) {
            float rm = fmaxf(fmaxf(s[i][0], s[i][1]), fmaxf(s[i][2], s[i][3]));
            #pragma unroll
            for (int o = 8; o > 0; o >>= 1)
                rm = fmaxf(rm, __shfl_xor_sync(0xffffffffu, rm, o));
            const float mnew = fmaxf(mrow[i], rm);
            const float alpha = (mrow[i] == -INFINITY) ? 0.f : __expf(mrow[i] - mnew);
            float p[4], ps = 0.f;
            #pragma unroll
            for (int j = 0; j < 4; j++) {
                p[j] = (s[i][j] == -INFINITY) ? 0.f : __expf(s[i][j] - mnew);
                ps += p[j];
            }
            #pragma unroll
            for (int o = 8; o > 0; o >>= 1)
                ps += __shfl_xor_sync(0xffffffffu, ps, o);
            lrow[i] = lrow[i] * alpha + ps;
            mrow[i] = mnew;
            #pragma unroll
            for (int j = 0; j < 4; j++) {
                acc[i][j] *= alpha;
                Pt[(tx*4 + j)*64 + ty*4 + i] = p[j];
            }
        }
        __syncwarp();

        #pragma unroll 8
        for (int k = 0; k < 64; k++) {
            float4 pv = *(const float4*)(Pt + k*64 + ty*4);
            float4 vv = *(const float4*)(Vs + k*64 + tx*4);
            const float pa[4] = {pv.x, pv.y, pv.z, pv.w};
            const float vb[4] = {vv.x, vv.y, vv.z, vv.w};
            #pragma unroll
            for (int i = 0; i < 4; i++)
                #pragma unroll
                for (int j = 0; j < 4; j++)
                    acc[i][j] = fmaf(pa[i], vb[j], acc[i][j]);
        }
    }

    #pragma unroll
    for (int i = 0; i < 4; i++) {
        const float rinv = (lrow[i] > 0.f) ? 1.f / lrow[i] : 0.f;
        const int qr = qt*64 + ty*4 + i;
        float4 o;
        o.x = acc[i][0] * rinv;
        o.y = acc[i][1] * rinv;
        o.z = acc[i][2] * rinv;
        o.w = acc[i][3] * rinv;
        *(float4*)(g_att + ((size_t)b*SS + qr)*DD + h*HD + tx*4) = o;
    }
}

// ---------------------------------------------------------------------------
extern "C" void kernel_launch(void* const* d_in, const int* in_sizes, int n_in,
                              void* d_out, int out_size)
{
    const float*     x   = (const float*)d_in[0];
    const long long* ids = (const long long*)d_in[1];
    const float*     Wq  = (const float*)d_in[2];
    const float*     bq  = (const float*)d_in[3];
    const float*     Wk  = (const float*)d_in[4];
    const float*     bk  = (const float*)d_in[5];
    const float*     Wv  = (const float*)d_in[6];
    const float*     bv  = (const float*)d_in[7];
    const float*     Wo  = (const float*)d_in[8];
    const float*     bo  = (const float*)d_in[9];
    float* out = (float*)d_out;

    float *q, *k, *v, *att;
    cudaGetSymbolAddress((void**)&q,   g_q);
    cudaGetSymbolAddress((void**)&k,   g_k);
    cudaGetSymbolAddress((void**)&v,   g_v);
    cudaGetSymbolAddress((void**)&att, g_att);
    __nv_bfloat16 *xc, *ac, *wqc, *wkc, *wvc, *woc;
    cudaGetSymbolAddress((void**)&xc,  g_xc);
    cudaGetSymbolAddress((void**)&ac,  g_ac);
    cudaGetSymbolAddress((void**)&wqc, g_wqc);
    cudaGetSymbolAddress((void**)&wkc, g_wkc);
    cudaGetSymbolAddress((void**)&wvc, g_wvc);
    cudaGetSymbolAddress((void**)&woc, g_woc);

    const int gemm_smem = STAGES * 32768;   // 128KB
    cudaFuncSetAttribute(gemm_bf16, cudaFuncAttributeMaxDynamicSharedMemorySize, gemm_smem);
    cudaFuncSetAttribute(flash_attn, cudaFuncAttributeMaxDynamicSharedMemorySize, 65536);

    // Pack operands to split-bf16
    convert_split<<<(MROWS*128)/256, 256>>>(x,  xc,  MROWS);
    convert_split<<<(DD*128)/256,    256>>>(Wq, wqc, DD);
    convert_split<<<(DD*128)/256,    256>>>(Wk, wkc, DD);
    convert_split<<<(DD*128)/256,    256>>>(Wv, wvc, DD);
    convert_split<<<(DD*128)/256,    256>>>(Wo, woc, DD);

    const dim3 gg(DD/128, MROWS/128);   // (8, 64)
    gemm_bf16<<<gg, 256, gemm_smem>>>(xc, wqc, bq, q, 1);
    gemm_bf16<<<gg, 256, gemm_smem>>>(xc, wkc, bk, k, 1);
    gemm_bf16<<<gg, 256, gemm_smem>>>(xc, wvc, bv, v, 1);

    flash_attn<<<dim3(SS/64, HH, BB), 256, 65536>>>(ids);

    convert_split<<<(MROWS*128)/256, 256>>>(att, ac, MROWS);
    gemm_bf16<<<gg, 256, gemm_smem>>>(ac, woc, bo, out, 0);
}

// round 5
// speedup vs baseline: 2.9087x; 1.6511x over previous
#include <cuda_runtime.h>
#include <cuda_bf16.h>
#include <math.h>
#include <stdint.h>

// Problem constants
#define BB   8
#define SS   1024
#define DD   1024
#define HH   16
#define HD   64
#define MROWS (BB*SS)   // 8192
#define NCHUNK 32       // K / 32
#define STAGES 4
#define NEG_INF (-INFINITY)

// Scratch (allocation-free rule: __device__ globals)
// Packed bf16 hi/lo GEMM operands: layout [row][kchunk(32)][hi 32 bf16 | lo 32 bf16]
__device__ __nv_bfloat16 g_xc [MROWS*2048];
__device__ __nv_bfloat16 g_ac [MROWS*2048];   // attention out, packed (written by flash)
__device__ __nv_bfloat16 g_wqc[DD*2048];
__device__ __nv_bfloat16 g_wkc[DD*2048];
__device__ __nv_bfloat16 g_wvc[DD*2048];
__device__ __nv_bfloat16 g_woc[DD*2048];
// Split QKV planes [B,H,S,HD] bf16 (Q pre-scaled by 0.125): B*H*S*HD = MROWS*DD
__device__ __nv_bfloat16 g_qh[MROWS*DD], g_ql[MROWS*DD];
__device__ __nv_bfloat16 g_kh[MROWS*DD], g_kl[MROWS*DD];
__device__ __nv_bfloat16 g_vh[MROWS*DD], g_vl[MROWS*DD];
// Pad-mask bias per key position: 0 or -INF
__device__ float g_vb[MROWS];

// ---------------------------------------------------------------------------
// PTX helpers
// ---------------------------------------------------------------------------
__device__ __forceinline__ uint32_t smem_u32(const void* p) {
    uint32_t a;
    asm("{ .reg .u64 t; cvta.to.shared.u64 t, %1; cvt.u32.u64 %0, t; }" : "=r"(a) : "l"(p));
    return a;
}
__device__ __forceinline__ void cp16(uint32_t dst, const void* src) {
    asm volatile("cp.async.cg.shared.global [%0], [%1], 16;" :: "r"(dst), "l"(src));
}
#define CP_COMMIT() asm volatile("cp.async.commit_group;" ::: "memory")
#define CP_WAIT(n)  asm volatile("cp.async.wait_group %0;" :: "n"(n) : "memory")

__device__ __forceinline__ void ldsm4(uint32_t* r, uint32_t addr) {
    asm volatile("ldmatrix.sync.aligned.m8n8.x4.shared.b16 {%0,%1,%2,%3}, [%4];"
                 : "=r"(r[0]), "=r"(r[1]), "=r"(r[2]), "=r"(r[3]) : "r"(addr));
}
__device__ __forceinline__ void ldsm4t(uint32_t* r, uint32_t addr) {
    asm volatile("ldmatrix.sync.aligned.m8n8.x4.trans.shared.b16 {%0,%1,%2,%3}, [%4];"
                 : "=r"(r[0]), "=r"(r[1]), "=r"(r[2]), "=r"(r[3]) : "r"(addr));
}
__device__ __forceinline__ void mma_bf16(float* d, const uint32_t* a, const uint32_t* b) {
    asm volatile("mma.sync.aligned.m16n8k16.row.col.f32.bf16.bf16.f32 "
                 "{%0,%1,%2,%3}, {%4,%5,%6,%7}, {%8,%9}, {%0,%1,%2,%3};"
                 : "+f"(d[0]), "+f"(d[1]), "+f"(d[2]), "+f"(d[3])
                 : "r"(a[0]), "r"(a[1]), "r"(a[2]), "r"(a[3]), "r"(b[0]), "r"(b[1]));
}
__device__ __forceinline__ uint32_t pack2(float lo, float hi) {
    __nv_bfloat162 h = __float22bfloat162_rn(make_float2(lo, hi));
    uint32_t u; memcpy(&u, &h, 4); return u;
}
__device__ __forceinline__ void splitpack(float x, float y, uint32_t& hi, uint32_t& lo) {
    __nv_bfloat162 h2 = __float22bfloat162_rn(make_float2(x, y));
    memcpy(&hi, &h2, 4);
    lo = pack2(x - __bfloat162float(h2.x), y - __bfloat162float(h2.y));
}

// ---------------------------------------------------------------------------
// Split-convert: fp32 [rows][1024] -> packed bf16 [rows][32][hi32|lo32]
// ---------------------------------------------------------------------------
__global__ __launch_bounds__(256) void convert_split(
    const float* __restrict__ in, __nv_bfloat16* __restrict__ out, int rows)
{
    const int g = blockIdx.x * 256 + threadIdx.x;
    if (g >= rows * 128) return;
    const int row  = g >> 7;
    const int w    = g & 127;
    const int kc   = w >> 2;
    const int part = w & 3;

    const float* src = in + (size_t)row * 1024 + kc * 32 + part * 8;
    float4 f0 = *(const float4*)(src);
    float4 f1 = *(const float4*)(src + 4);
    const float xs[8] = {f0.x, f0.y, f0.z, f0.w, f1.x, f1.y, f1.z, f1.w};

    alignas(16) __nv_bfloat16 h[8];
    alignas(16) __nv_bfloat16 l[8];
    #pragma unroll
    for (int e = 0; e < 8; e++) {
        h[e] = __float2bfloat16_rn(xs[e]);
        l[e] = __float2bfloat16_rn(xs[e] - __bfloat162float(h[e]));
    }
    __nv_bfloat16* dst = out + ((size_t)row * 32 + kc) * 64 + part * 8;
    *(uint4*)(dst)      = *(const uint4*)h;
    *(uint4*)(dst + 32) = *(const uint4*)l;
}

// Pad-mask: vb[i] = ids[i]!=1 ? 0 : -INF
__global__ void pad_mask(const long long* __restrict__ ids, float* __restrict__ vb) {
    int i = blockIdx.x * 256 + threadIdx.x;
    if (i < MROWS) vb[i] = (ids[i] != 1LL) ? 0.f : NEG_INF;
}

// ---------------------------------------------------------------------------
// bf16 3-term split GEMM via mma.sync: C[M,N] = A[M,K]*W[N,K]^T + bias, *scale
// mode 0: fp32 out [M,N].  mode 1: split bf16 planes [B,H,S,HD].
// ---------------------------------------------------------------------------
__global__ __launch_bounds__(256) void gemm_bf16(
    const __nv_bfloat16* __restrict__ Ap, const __nv_bfloat16* __restrict__ Bp,
    const float* __restrict__ bias, float* __restrict__ outf,
    __nv_bfloat16* __restrict__ oh, __nv_bfloat16* __restrict__ ol,
    float scale, int mode)
{
    extern __shared__ char dsm[];
    const uint32_t smem_base = smem_u32(dsm);

    const int tid  = threadIdx.x;
    const int wid  = tid >> 5;
    const int lane = tid & 31;
    const int bm   = blockIdx.y << 7;
    const int bn   = blockIdx.x << 7;

    const int wm = (wid & 3) << 5;
    const int wn = (wid >> 2) << 6;

    auto load_stage = [&](int kc, int s) {
        const uint32_t sA = smem_base + s * 32768;
        const uint32_t sB = sA + 16384;
        #pragma unroll
        for (int v = 0; v < 4; v++) {
            const int cid = v * 256 + tid;
            const int row = cid >> 3;
            const int c   = cid & 7;
            const uint32_t so = row * 128 + ((c ^ (row & 7)) << 4);
            cp16(sA + so, Ap + (((size_t)(bm + row) * 32 + kc) << 6) + c * 8);
            cp16(sB + so, Bp + (((size_t)(bn + row) * 32 + kc) << 6) + c * 8);
        }
        CP_COMMIT();
    };

    float acc[2][8][4];
    #pragma unroll
    for (int i = 0; i < 2; i++)
        #pragma unroll
        for (int j = 0; j < 8; j++)
            #pragma unroll
            for (int e = 0; e < 4; e++) acc[i][j][e] = 0.f;

    load_stage(0, 0);
    load_stage(1, 1);
    load_stage(2, 2);

    for (int i = 0; i < NCHUNK; i++) {
        CP_WAIT(2);
        __syncthreads();

        const int s = i & (STAGES - 1);
        const uint32_t sA = smem_base + s * 32768;
        const uint32_t sB = sA + 16384;

        #pragma unroll
        for (int ks = 0; ks < 2; ks++) {
            uint32_t Ah[2][4], Al[2][4], Bh[8][2], Bl[8][2];
            const int chi = ks * 2 + (lane >> 4);
            const int clo = chi + 4;

            #pragma unroll
            for (int f = 0; f < 2; f++) {
                const int r = wm + f * 16 + (lane & 15);
                const uint32_t rb = sA + r * 128;
                ldsm4(Ah[f], rb + ((chi ^ (r & 7)) << 4));
                ldsm4(Al[f], rb + ((clo ^ (r & 7)) << 4));
            }
            #pragma unroll
            for (int p = 0; p < 4; p++) {
                const int r = wn + p * 16 + (lane & 15);
                const uint32_t rb = sB + r * 128;
                uint32_t q[4];
                ldsm4(q, rb + ((chi ^ (r & 7)) << 4));
                Bh[2*p][0] = q[0]; Bh[2*p][1] = q[2];
                Bh[2*p+1][0] = q[1]; Bh[2*p+1][1] = q[3];
                ldsm4(q, rb + ((clo ^ (r & 7)) << 4));
                Bl[2*p][0] = q[0]; Bl[2*p][1] = q[2];
                Bl[2*p+1][0] = q[1]; Bl[2*p+1][1] = q[3];
            }

            #pragma unroll
            for (int f = 0; f < 2; f++)
                #pragma unroll
                for (int j = 0; j < 8; j++) {
                    mma_bf16(acc[f][j], Ah[f], Bh[j]);
                    mma_bf16(acc[f][j], Ah[f], Bl[j]);
                    mma_bf16(acc[f][j], Al[f], Bh[j]);
                }
        }

        __syncthreads();
        if (i + STAGES - 1 < NCHUNK)
            load_stage(i + STAGES - 1, (i + STAGES - 1) & (STAGES - 1));
    }

    #pragma unroll
    for (int f = 0; f < 2; f++) {
        #pragma unroll
        for (int j = 0; j < 8; j++) {
            const int col = bn + wn + j * 8 + ((lane & 3) << 1);
            const float b0 = bias[col], b1 = bias[col + 1];
            #pragma unroll
            for (int half = 0; half < 2; half++) {
                const int m = bm + wm + f * 16 + (lane >> 2) + half * 8;
                float2 o;
                o.x = (acc[f][j][half * 2 + 0] + b0) * scale;
                o.y = (acc[f][j][half * 2 + 1] + b1) * scale;
                if (mode == 0) {
                    *(float2*)(outf + (size_t)m * DD + col) = o;
                } else {
                    const int b_ = m >> 10, s_ = m & 1023;
                    const int h_ = col >> 6, d_ = col & 63;
                    const size_t idx = ((size_t)(b_ * HH + h_) * SS + s_) * HD + d_;
                    uint32_t hi, lo;
                    splitpack(o.x, o.y, hi, lo);
                    *(uint32_t*)(oh + idx) = hi;
                    *(uint32_t*)(ol + idx) = lo;
                }
            }
        }
    }
}

// ---------------------------------------------------------------------------
// Flash attention, bf16 mma.sync with 3-term splits.
// Block: 128 threads (4 warps) = 64 query rows of one (b,h). Grid (16,16,8).
// Warp w owns query rows w*16..w*16+15. Online softmax in fp32 registers.
// smem: Qh/Ql (8KB each), vbias (4KB), 2 stages x {Kh,Kl,Vh,Vl} (32KB each).
// Output written directly into packed split layout g_ac for the final GEMM.
// ---------------------------------------------------------------------------
__global__ __launch_bounds__(128) void flash_bf16(
    const __nv_bfloat16* __restrict__ qh, const __nv_bfloat16* __restrict__ ql,
    const __nv_bfloat16* __restrict__ kh, const __nv_bfloat16* __restrict__ kl,
    const __nv_bfloat16* __restrict__ vh, const __nv_bfloat16* __restrict__ vl,
    const float* __restrict__ vb, __nv_bfloat16* __restrict__ outp)
{
    extern __shared__ char dsm[];
    const uint32_t sb = smem_u32(dsm);

    const int tid  = threadIdx.x;
    const int wid  = tid >> 5;
    const int lane = tid & 31;
    const int qt = blockIdx.x, h = blockIdx.y, b = blockIdx.z;
    const size_t bhrow = ((size_t)b * HH + h) * SS;   // plane row base

    const uint32_t sQh = sb, sQl = sb + 8192;
    const uint32_t sVB = sb + 16384;                  // 1024 floats
    const float* svp = (const float*)(dsm + 16384);
    const uint32_t stage_base = sb + 20480;           // + s*32768

    auto ldplane = [&](uint32_t dst, const __nv_bfloat16* src) {
        #pragma unroll
        for (int v = 0; v < 4; v++) {
            const int cid = v * 128 + tid;
            const int row = cid >> 3, c = cid & 7;
            cp16(dst + row * 128 + ((c ^ (row & 7)) << 4),
                 src + (size_t)row * 64 + c * 8);
        }
    };
    auto load_stage = [&](int kt, int s) {
        const uint32_t st = stage_base + (uint32_t)s * 32768;
        const size_t ro = (bhrow + (size_t)kt * 64) * 64;
        ldplane(st,         kh + ro);
        ldplane(st + 8192,  kl + ro);
        ldplane(st + 16384, vh + ro);
        ldplane(st + 24576, vl + ro);
        CP_COMMIT();
    };

    // prologue: Q + pad-bias, then K/V stage 0
    {
        const size_t qo = (bhrow + (size_t)qt * 64) * 64;
        ldplane(sQh, qh + qo);
        ldplane(sQl, ql + qo);
        #pragma unroll
        for (int v = 0; v < 2; v++) {
            const int cid = v * 128 + tid;
            cp16(sVB + cid * 16, vb + (size_t)b * SS + cid * 4);
        }
        CP_COMMIT();
    }
    load_stage(0, 0);

    uint32_t Qh[4][4], Ql[4][4];
    float O[8][4];
    #pragma unroll
    for (int j = 0; j < 8; j++)
        #pragma unroll
        for (int e = 0; e < 4; e++) O[j][e] = 0.f;
    float mrow0 = NEG_INF, mrow1 = NEG_INF, lrow0 = 0.f, lrow1 = 0.f;

    const int grp = lane >> 3, rw = lane & 7;
    const int c0  = (lane & 3) << 1;
    const int qr0 = wid * 16 + (lane >> 2);
    const int qr1 = qr0 + 8;

    for (int kt = 0; kt <= qt; kt++) {
        const int s = kt & 1;
        if (kt < qt) { load_stage(kt + 1, s ^ 1); CP_WAIT(1); }
        else         { CP_WAIT(0); }
        __syncthreads();

        if (kt == 0) {
            #pragma unroll
            for (int ks = 0; ks < 4; ks++) {
                const int row = wid * 16 + (grp & 1) * 8 + rw;
                const int ch  = 2 * ks + (grp >> 1);
                const uint32_t off = row * 128 + ((ch ^ (row & 7)) << 4);
                ldsm4(Qh[ks], sQh + off);
                ldsm4(Ql[ks], sQl + off);
            }
        }

        const uint32_t stK = stage_base + (uint32_t)s * 32768;
        const uint32_t stV = stK + 16384;

        // ---- S = Q.K^T (3-term split), 16x64 per warp
        float S[8][4];
        #pragma unroll
        for (int j = 0; j < 8; j++)
            #pragma unroll
            for (int e = 0; e < 4; e++) S[j][e] = 0.f;

        #pragma unroll
        for (int ks = 0; ks < 4; ks++) {
            uint32_t Bh[8][2], Bl[8][2];
            #pragma unroll
            for (int jp = 0; jp < 4; jp++) {
                const int row = jp * 16 + (grp >> 1) * 8 + rw;
                const int ch  = 2 * ks + (grp & 1);
                const uint32_t off = row * 128 + ((ch ^ (row & 7)) << 4);
                uint32_t t[4];
                ldsm4(t, stK + off);
                Bh[2*jp][0] = t[0]; Bh[2*jp][1] = t[1];
                Bh[2*jp+1][0] = t[2]; Bh[2*jp+1][1] = t[3];
                ldsm4(t, stK + 8192 + off);
                Bl[2*jp][0] = t[0]; Bl[2*jp][1] = t[1];
                Bl[2*jp+1][0] = t[2]; Bl[2*jp+1][1] = t[3];
            }
            #pragma unroll
            for (int j = 0; j < 8; j++) {
                mma_bf16(S[j], Qh[ks], Bh[j]);
                mma_bf16(S[j], Qh[ks], Bl[j]);
                mma_bf16(S[j], Ql[ks], Bh[j]);
            }
        }

        // ---- mask + online softmax
        #pragma unroll
        for (int j = 0; j < 8; j++) {
            const int k0 = j * 8 + c0, k1 = k0 + 1;
            const float p0 = svp[kt * 64 + k0];
            const float p1 = svp[kt * 64 + k1];
            S[j][0] += p0; S[j][1] += p1; S[j][2] += p0; S[j][3] += p1;
            if (kt == qt) {
                if (k0 > qr0) S[j][0] = NEG_INF;
                if (k1 > qr0) S[j][1] = NEG_INF;
                if (k0 > qr1) S[j][2] = NEG_INF;
                if (k1 > qr1) S[j][3] = NEG_INF;
            }
        }
        float rm0 = NEG_INF, rm1 = NEG_INF;
        #pragma unroll
        for (int j = 0; j < 8; j++) {
            rm0 = fmaxf(rm0, fmaxf(S[j][0], S[j][1]));
            rm1 = fmaxf(rm1, fmaxf(S[j][2], S[j][3]));
        }
        rm0 = fmaxf(rm0, __shfl_xor_sync(0xffffffffu, rm0, 1));
        rm0 = fmaxf(rm0, __shfl_xor_sync(0xffffffffu, rm0, 2));
        rm1 = fmaxf(rm1, __shfl_xor_sync(0xffffffffu, rm1, 1));
        rm1 = fmaxf(rm1, __shfl_xor_sync(0xffffffffu, rm1, 2));

        const float mn0 = fmaxf(mrow0, rm0);
        const float mn1 = fmaxf(mrow1, rm1);
        const float al0 = (mrow0 == NEG_INF) ? 0.f : __expf(mrow0 - mn0);
        const float al1 = (mrow1 == NEG_INF) ? 0.f : __expf(mrow1 - mn1);

        float ps0 = 0.f, ps1 = 0.f;
        #pragma unroll
        for (int j = 0; j < 8; j++) {
            float p;
            p = (S[j][0] == NEG_INF) ? 0.f : __expf(S[j][0] - mn0); S[j][0] = p; ps0 += p;
            p = (S[j][1] == NEG_INF) ? 0.f : __expf(S[j][1] - mn0); S[j][1] = p; ps0 += p;
            p = (S[j][2] == NEG_INF) ? 0.f : __expf(S[j][2] - mn1); S[j][2] = p; ps1 += p;
            p = (S[j][3] == NEG_INF) ? 0.f : __expf(S[j][3] - mn1); S[j][3] = p; ps1 += p;
        }
        ps0 += __shfl_xor_sync(0xffffffffu, ps0, 1);
        ps0 += __shfl_xor_sync(0xffffffffu, ps0, 2);
        ps1 += __shfl_xor_sync(0xffffffffu, ps1, 1);
        ps1 += __shfl_xor_sync(0xffffffffu, ps1, 2);

        lrow0 = lrow0 * al0 + ps0; mrow0 = mn0;
        lrow1 = lrow1 * al1 + ps1; mrow1 = mn1;
        #pragma unroll
        for (int j = 0; j < 8; j++) {
            O[j][0] *= al0; O[j][1] *= al0;
            O[j][2] *= al1; O[j][3] *= al1;
        }

        // ---- O += P.V (3-term split)
        #pragma unroll
        for (int ks = 0; ks < 4; ks++) {
            uint32_t Ph[4], Pl[4];
            splitpack(S[2*ks][0],   S[2*ks][1],   Ph[0], Pl[0]);
            splitpack(S[2*ks][2],   S[2*ks][3],   Ph[1], Pl[1]);
            splitpack(S[2*ks+1][0], S[2*ks+1][1], Ph[2], Pl[2]);
            splitpack(S[2*ks+1][2], S[2*ks+1][3], Ph[3], Pl[3]);

            uint32_t Vh[8][2], Vl[8][2];
            #pragma unroll
            for (int jp = 0; jp < 4; jp++) {
                const int row = ks * 16 + (grp & 1) * 8 + rw;
                const int ch  = 2 * jp + (grp >> 1);
                const uint32_t off = row * 128 + ((ch ^ (row & 7)) << 4);
                uint32_t t[4];
                ldsm4t(t, stV + off);
                Vh[2*jp][0] = t[0]; Vh[2*jp][1] = t[1];
                Vh[2*jp+1][0] = t[2]; Vh[2*jp+1][1] = t[3];
                ldsm4t(t, stV + 8192 + off);
                Vl[2*jp][0] = t[0]; Vl[2*jp][1] = t[1];
                Vl[2*jp+1][0] = t[2]; Vl[2*jp+1][1] = t[3];
            }
            #pragma unroll
            for (int j = 0; j < 8; j++) {
                mma_bf16(O[j], Ph, Vh[j]);
                mma_bf16(O[j], Ph, Vl[j]);
                mma_bf16(O[j], Pl, Vh[j]);
            }
        }
        __syncthreads();   // stage consumers done before next prefetch overwrites
    }

    // ---- epilogue: normalize, split, write packed g_ac
    const float ri0 = (lrow0 > 0.f) ? 1.f / lrow0 : 0.f;
    const float ri1 = (lrow1 > 0.f) ? 1.f / lrow1 : 0.f;
    const int m0 = b * 1024 + qt * 64 + qr0;
    const int m1 = m0 + 8;
    #pragma unroll
    for (int j = 0; j < 8; j++) {
        const int col = h * 64 + j * 8 + c0;
        const int chunk = col >> 5, wc = col & 31;
        uint32_t hi, lo;
        splitpack(O[j][0] * ri0, O[j][1] * ri0, hi, lo);
        size_t base = ((size_t)m0 * 32 + chunk) * 64 + wc;
        *(uint32_t*)(outp + base)      = hi;
        *(uint32_t*)(outp + base + 32) = lo;
        splitpack(O[j][2] * ri1, O[j][3] * ri1, hi, lo);
        base = ((size_t)m1 * 32 + chunk) * 64 + wc;
        *(uint32_t*)(outp + base)      = hi;
        *(uint32_t*)(outp + base + 32) = lo;
    }
}

// ---------------------------------------------------------------------------
extern "C" void kernel_launch(void* const* d_in, const int* in_sizes, int n_in,
                              void* d_out, int out_size)
{
    const float*     x   = (const float*)d_in[0];
    const long long* ids = (const long long*)d_in[1];
    const float*     Wq  = (const float*)d_in[2];
    const float*     bq  = (const float*)d_in[3];
    const float*     Wk  = (const float*)d_in[4];
    const float*     bk  = (const float*)d_in[5];
    const float*     Wv  = (const float*)d_in[6];
    const float*     bv  = (const float*)d_in[7];
    const float*     Wo  = (const float*)d_in[8];
    const float*     bo  = (const float*)d_in[9];
    float* out = (float*)d_out;

    __nv_bfloat16 *xc, *ac, *wqc, *wkc, *wvc, *woc;
    __nv_bfloat16 *qh, *ql, *kh, *kl, *vh, *vl;
    float* vb;
    cudaGetSymbolAddress((void**)&xc,  g_xc);
    cudaGetSymbolAddress((void**)&ac,  g_ac);
    cudaGetSymbolAddress((void**)&wqc, g_wqc);
    cudaGetSymbolAddress((void**)&wkc, g_wkc);
    cudaGetSymbolAddress((void**)&wvc, g_wvc);
    cudaGetSymbolAddress((void**)&woc, g_woc);
    cudaGetSymbolAddress((void**)&qh,  g_qh);
    cudaGetSymbolAddress((void**)&ql,  g_ql);
    cudaGetSymbolAddress((void**)&kh,  g_kh);
    cudaGetSymbolAddress((void**)&kl,  g_kl);
    cudaGetSymbolAddress((void**)&vh,  g_vh);
    cudaGetSymbolAddress((void**)&vl,  g_vl);
    cudaGetSymbolAddress((void**)&vb,  g_vb);

    const int gemm_smem  = STAGES * 32768;        // 128KB
    const int flash_smem = 20480 + 2 * 32768;     // 86KB
    cudaFuncSetAttribute(gemm_bf16, cudaFuncAttributeMaxDynamicSharedMemorySize, gemm_smem);
    cudaFuncSetAttribute(flash_bf16, cudaFuncAttributeMaxDynamicSharedMemorySize, flash_smem);

    convert_split<<<(MROWS*128)/256, 256>>>(x,  xc,  MROWS);
    convert_split<<<(DD*128)/256,    256>>>(Wq, wqc, DD);
    convert_split<<<(DD*128)/256,    256>>>(Wk, wkc, DD);
    convert_split<<<(DD*128)/256,    256>>>(Wv, wvc, DD);
    convert_split<<<(DD*128)/256,    256>>>(Wo, woc, DD);
    pad_mask<<<MROWS/256, 256>>>(ids, vb);

    const dim3 gg(DD/128, MROWS/128);   // (8, 64)
    gemm_bf16<<<gg, 256, gemm_smem>>>(xc, wqc, bq, nullptr, qh, ql, 0.125f, 1);
    gemm_bf16<<<gg, 256, gemm_smem>>>(xc, wkc, bk, nullptr, kh, kl, 1.f,    1);
    gemm_bf16<<<gg, 256, gemm_smem>>>(xc, wvc, bv, nullptr, vh, vl, 1.f,    1);

    flash_bf16<<<dim3(16, 16, 8), 128, flash_smem>>>(qh, ql, kh, kl, vh, vl, vb, ac);

    gemm_bf16<<<gg, 256, gemm_smem>>>(ac, woc, bo, out, nullptr, nullptr, 1.f, 0);
}

// round 6
// speedup vs baseline: 3.5154x; 1.2086x over previous
#include <cuda_runtime.h>
#include <cuda_bf16.h>
#include <math.h>
#include <stdint.h>

// Problem constants
#define BB   8
#define SS   1024
#define DD   1024
#define HH   16
#define HD   64
#define MROWS (BB*SS)   // 8192
#define NCHUNK 32       // K / 32
#define NEG_INF (-INFINITY)

// Scratch (allocation-free rule: __device__ globals)
// Packed bf16 hi/lo GEMM operands: layout [row][kchunk(32)][hi 32 bf16 | lo 32 bf16]
__device__ __nv_bfloat16 g_xc [MROWS*2048];
__device__ __nv_bfloat16 g_ac [MROWS*2048];   // attention out, packed (written by flash)
__device__ __nv_bfloat16 g_wqc[DD*2048];
__device__ __nv_bfloat16 g_wkc[DD*2048];
__device__ __nv_bfloat16 g_wvc[DD*2048];
__device__ __nv_bfloat16 g_woc[DD*2048];
// Split QKV planes [B,H,S,HD] bf16 (Q pre-scaled by 0.125): B*H*S*HD = MROWS*DD
__device__ __nv_bfloat16 g_qh[MROWS*DD], g_ql[MROWS*DD];
__device__ __nv_bfloat16 g_kh[MROWS*DD], g_kl[MROWS*DD];
__device__ __nv_bfloat16 g_vh[MROWS*DD], g_vl[MROWS*DD];
// Pad-mask bias per key position: 0 or -INF
__device__ float g_vb[MROWS];

// ---------------------------------------------------------------------------
// PTX helpers
// ---------------------------------------------------------------------------
__device__ __forceinline__ uint32_t smem_u32(const void* p) {
    uint32_t a;
    asm("{ .reg .u64 t; cvta.to.shared.u64 t, %1; cvt.u32.u64 %0, t; }" : "=r"(a) : "l"(p));
    return a;
}
__device__ __forceinline__ void cp16(uint32_t dst, const void* src) {
    asm volatile("cp.async.cg.shared.global [%0], [%1], 16;" :: "r"(dst), "l"(src));
}
#define CP_COMMIT() asm volatile("cp.async.commit_group;" ::: "memory")
#define CP_WAIT(n)  asm volatile("cp.async.wait_group %0;" :: "n"(n) : "memory")

__device__ __forceinline__ void ldsm4(uint32_t* r, uint32_t addr) {
    asm volatile("ldmatrix.sync.aligned.m8n8.x4.shared.b16 {%0,%1,%2,%3}, [%4];"
                 : "=r"(r[0]), "=r"(r[1]), "=r"(r[2]), "=r"(r[3]) : "r"(addr));
}
__device__ __forceinline__ void ldsm4t(uint32_t* r, uint32_t addr) {
    asm volatile("ldmatrix.sync.aligned.m8n8.x4.trans.shared.b16 {%0,%1,%2,%3}, [%4];"
                 : "=r"(r[0]), "=r"(r[1]), "=r"(r[2]), "=r"(r[3]) : "r"(addr));
}
__device__ __forceinline__ void mma_bf16(float* d, const uint32_t* a, const uint32_t* b) {
    asm volatile("mma.sync.aligned.m16n8k16.row.col.f32.bf16.bf16.f32 "
                 "{%0,%1,%2,%3}, {%4,%5,%6,%7}, {%8,%9}, {%0,%1,%2,%3};"
                 : "+f"(d[0]), "+f"(d[1]), "+f"(d[2]), "+f"(d[3])
                 : "r"(a[0]), "r"(a[1]), "r"(a[2]), "r"(a[3]), "r"(b[0]), "r"(b[1]));
}
__device__ __forceinline__ uint32_t pack2(float lo, float hi) {
    __nv_bfloat162 h = __float22bfloat162_rn(make_float2(lo, hi));
    uint32_t u; memcpy(&u, &h, 4); return u;
}
__device__ __forceinline__ void splitpack(float x, float y, uint32_t& hi, uint32_t& lo) {
    __nv_bfloat162 h2 = __float22bfloat162_rn(make_float2(x, y));
    memcpy(&hi, &h2, 4);
    lo = pack2(x - __bfloat162float(h2.x), y - __bfloat162float(h2.y));
}

// ---------------------------------------------------------------------------
// Split-convert: fp32 [rows][1024] -> packed bf16 [rows][32][hi32|lo32]
// ---------------------------------------------------------------------------
__global__ __launch_bounds__(256) void convert_split(
    const float* __restrict__ in, __nv_bfloat16* __restrict__ out, int rows)
{
    const int g = blockIdx.x * 256 + threadIdx.x;
    if (g >= rows * 128) return;
    const int row  = g >> 7;
    const int w    = g & 127;
    const int kc   = w >> 2;
    const int part = w & 3;

    const float* src = in + (size_t)row * 1024 + kc * 32 + part * 8;
    float4 f0 = *(const float4*)(src);
    float4 f1 = *(const float4*)(src + 4);
    const float xs[8] = {f0.x, f0.y, f0.z, f0.w, f1.x, f1.y, f1.z, f1.w};

    alignas(16) __nv_bfloat16 h[8];
    alignas(16) __nv_bfloat16 l[8];
    #pragma unroll
    for (int e = 0; e < 8; e++) {
        h[e] = __float2bfloat16_rn(xs[e]);
        l[e] = __float2bfloat16_rn(xs[e] - __bfloat162float(h[e]));
    }
    __nv_bfloat16* dst = out + ((size_t)row * 32 + kc) * 64 + part * 8;
    *(uint4*)(dst)      = *(const uint4*)h;
    *(uint4*)(dst + 32) = *(const uint4*)l;
}

// Pad-mask: vb[i] = ids[i]!=1 ? 0 : -INF
__global__ void pad_mask(const long long* __restrict__ ids, float* __restrict__ vb) {
    int i = blockIdx.x * 256 + threadIdx.x;
    if (i < MROWS) vb[i] = (ids[i] != 1LL) ? 0.f : NEG_INF;
}

// ---------------------------------------------------------------------------
// GEMM core: bf16 3-term split via mma.sync. C = A*W^T (+bias)*scale.
// 128x128 tile, 256 threads, 3-stage cp.async pipeline (96KB smem),
// ONE __syncthreads per chunk. mode 0: fp32 [M,N]; mode 1: split planes.
// ---------------------------------------------------------------------------
__device__ __forceinline__ void gemm_core(
    const __nv_bfloat16* __restrict__ Ap, const __nv_bfloat16* __restrict__ Bp,
    const float* __restrict__ bias, float* __restrict__ outf,
    __nv_bfloat16* __restrict__ oh, __nv_bfloat16* __restrict__ ol,
    float scale, int mode, char* dsm, int bm, int bn)
{
    const uint32_t smem_base = smem_u32(dsm);
    const int tid  = threadIdx.x;
    const int wid  = tid >> 5;
    const int lane = tid & 31;
    const int wm = (wid & 3) << 5;
    const int wn = (wid >> 2) << 6;

    auto load_stage = [&](int kc, int s) {
        const uint32_t sA = smem_base + s * 32768;
        const uint32_t sB = sA + 16384;
        #pragma unroll
        for (int v = 0; v < 4; v++) {
            const int cid = v * 256 + tid;
            const int row = cid >> 3;
            const int c   = cid & 7;
            const uint32_t so = row * 128 + ((c ^ (row & 7)) << 4);
            cp16(sA + so, Ap + (((size_t)(bm + row) * 32 + kc) << 6) + c * 8);
            cp16(sB + so, Bp + (((size_t)(bn + row) * 32 + kc) << 6) + c * 8);
        }
        CP_COMMIT();
    };

    float acc[2][8][4];
    #pragma unroll
    for (int i = 0; i < 2; i++)
        #pragma unroll
        for (int j = 0; j < 8; j++)
            #pragma unroll
            for (int e = 0; e < 4; e++) acc[i][j][e] = 0.f;

    load_stage(0, 0);
    load_stage(1, 1);

    int stage = 0;
    for (int i = 0; i < NCHUNK; i++) {
        CP_WAIT(1);
        __syncthreads();

        const uint32_t sA = smem_base + stage * 32768;
        const uint32_t sB = sA + 16384;

        #pragma unroll
        for (int ks = 0; ks < 2; ks++) {
            uint32_t Ah[2][4], Al[2][4];
            const int chi = ks * 2 + (lane >> 4);
            const int clo = chi + 4;

            #pragma unroll
            for (int f = 0; f < 2; f++) {
                const int r = wm + f * 16 + (lane & 15);
                const uint32_t rb = sA + r * 128;
                ldsm4(Ah[f], rb + ((chi ^ (r & 7)) << 4));
                ldsm4(Al[f], rb + ((clo ^ (r & 7)) << 4));
            }
            #pragma unroll
            for (int ph = 0; ph < 2; ph++) {
                uint32_t Bh[4][2], Bl[4][2];
                #pragma unroll
                for (int pp = 0; pp < 2; pp++) {
                    const int p = ph * 2 + pp;
                    const int r = wn + p * 16 + (lane & 15);
                    const uint32_t rb = sB + r * 128;
                    uint32_t q[4];
                    ldsm4(q, rb + ((chi ^ (r & 7)) << 4));
                    Bh[2*pp][0] = q[0]; Bh[2*pp][1] = q[2];
                    Bh[2*pp+1][0] = q[1]; Bh[2*pp+1][1] = q[3];
                    ldsm4(q, rb + ((clo ^ (r & 7)) << 4));
                    Bl[2*pp][0] = q[0]; Bl[2*pp][1] = q[2];
                    Bl[2*pp+1][0] = q[1]; Bl[2*pp+1][1] = q[3];
                }
                #pragma unroll
                for (int f = 0; f < 2; f++)
                    #pragma unroll
                    for (int jj = 0; jj < 4; jj++) {
                        float* a = acc[f][ph * 4 + jj];
                        mma_bf16(a, Ah[f], Bh[jj]);
                        mma_bf16(a, Ah[f], Bl[jj]);
                        mma_bf16(a, Al[f], Bh[jj]);
                    }
            }
        }

        // prefetch chunk i+2 into the stage holding chunk i-1 (readers done:
        // everyone passed this iteration's top barrier)
        if (i + 2 < NCHUNK) {
            int ws = stage + 2; if (ws >= 3) ws -= 3;
            load_stage(i + 2, ws);
        }
        if (++stage == 3) stage = 0;
    }

    #pragma unroll
    for (int f = 0; f < 2; f++) {
        #pragma unroll
        for (int j = 0; j < 8; j++) {
            const int col = bn + wn + j * 8 + ((lane & 3) << 1);
            const float b0 = bias[col], b1 = bias[col + 1];
            #pragma unroll
            for (int half = 0; half < 2; half++) {
                const int m = bm + wm + f * 16 + (lane >> 2) + half * 8;
                float2 o;
                o.x = (acc[f][j][half * 2 + 0] + b0) * scale;
                o.y = (acc[f][j][half * 2 + 1] + b1) * scale;
                if (mode == 0) {
                    *(float2*)(outf + (size_t)m * DD + col) = o;
                } else {
                    const int b_ = m >> 10, s_ = m & 1023;
                    const int h_ = col >> 6, d_ = col & 63;
                    const size_t idx = ((size_t)(b_ * HH + h_) * SS + s_) * HD + d_;
                    uint32_t hi, lo;
                    splitpack(o.x, o.y, hi, lo);
                    *(uint32_t*)(oh + idx) = hi;
                    *(uint32_t*)(ol + idx) = lo;
                }
            }
        }
    }
}

// Fused QKV projections: grid (8, 64, 3); z selects weight/bias/output.
__global__ __launch_bounds__(256, 2) void gemm_qkv(
    const __nv_bfloat16* __restrict__ xc,
    const __nv_bfloat16* __restrict__ wq, const __nv_bfloat16* __restrict__ wk,
    const __nv_bfloat16* __restrict__ wv,
    const float* __restrict__ bq, const float* __restrict__ bk,
    const float* __restrict__ bv,
    __nv_bfloat16* qh, __nv_bfloat16* ql, __nv_bfloat16* kh,
    __nv_bfloat16* kl, __nv_bfloat16* vh, __nv_bfloat16* vl)
{
    extern __shared__ char dsm[];
    const int z = blockIdx.z;
    const __nv_bfloat16* Bp = (z == 0) ? wq : (z == 1) ? wk : wv;
    const float* bias       = (z == 0) ? bq : (z == 1) ? bk : bv;
    __nv_bfloat16* oh       = (z == 0) ? qh : (z == 1) ? kh : vh;
    __nv_bfloat16* ol       = (z == 0) ? ql : (z == 1) ? kl : vl;
    const float scale       = (z == 0) ? 0.125f : 1.f;
    gemm_core(xc, Bp, bias, nullptr, oh, ol, scale, 1, dsm,
              blockIdx.y << 7, blockIdx.x << 7);
}

// Output projection: fp32 out.
__global__ __launch_bounds__(256, 2) void gemm_ao(
    const __nv_bfloat16* __restrict__ ac, const __nv_bfloat16* __restrict__ woc,
    const float* __restrict__ bo, float* __restrict__ out)
{
    extern __shared__ char dsm[];
    gemm_core(ac, woc, bo, out, nullptr, nullptr, 1.f, 0, dsm,
              blockIdx.y << 7, blockIdx.x << 7);
}

// ---------------------------------------------------------------------------
// Flash attention, bf16 mma.sync with 3-term splits (unchanged from R5).
// ---------------------------------------------------------------------------
__global__ __launch_bounds__(128) void flash_bf16(
    const __nv_bfloat16* __restrict__ qh, const __nv_bfloat16* __restrict__ ql,
    const __nv_bfloat16* __restrict__ kh, const __nv_bfloat16* __restrict__ kl,
    const __nv_bfloat16* __restrict__ vh, const __nv_bfloat16* __restrict__ vl,
    const float* __restrict__ vb, __nv_bfloat16* __restrict__ outp)
{
    extern __shared__ char dsm[];
    const uint32_t sb = smem_u32(dsm);

    const int tid  = threadIdx.x;
    const int wid  = tid >> 5;
    const int lane = tid & 31;
    const int qt = blockIdx.x, h = blockIdx.y, b = blockIdx.z;
    const size_t bhrow = ((size_t)b * HH + h) * SS;

    const uint32_t sQh = sb, sQl = sb + 8192;
    const uint32_t sVB = sb + 16384;
    const float* svp = (const float*)(dsm + 16384);
    const uint32_t stage_base = sb + 20480;

    auto ldplane = [&](uint32_t dst, const __nv_bfloat16* src) {
        #pragma unroll
        for (int v = 0; v < 4; v++) {
            const int cid = v * 128 + tid;
            const int row = cid >> 3, c = cid & 7;
            cp16(dst + row * 128 + ((c ^ (row & 7)) << 4),
                 src + (size_t)row * 64 + c * 8);
        }
    };
    auto load_stage = [&](int kt, int s) {
        const uint32_t st = stage_base + (uint32_t)s * 32768;
        const size_t ro = (bhrow + (size_t)kt * 64) * 64;
        ldplane(st,         kh + ro);
        ldplane(st + 8192,  kl + ro);
        ldplane(st + 16384, vh + ro);
        ldplane(st + 24576, vl + ro);
        CP_COMMIT();
    };

    {
        const size_t qo = (bhrow + (size_t)qt * 64) * 64;
        ldplane(sQh, qh + qo);
        ldplane(sQl, ql + qo);
        #pragma unroll
        for (int v = 0; v < 2; v++) {
            const int cid = v * 128 + tid;
            cp16(sVB + cid * 16, vb + (size_t)b * SS + cid * 4);
        }
        CP_COMMIT();
    }
    load_stage(0, 0);

    uint32_t Qh[4][4], Ql[4][4];
    float O[8][4];
    #pragma unroll
    for (int j = 0; j < 8; j++)
        #pragma unroll
        for (int e = 0; e < 4; e++) O[j][e] = 0.f;
    float mrow0 = NEG_INF, mrow1 = NEG_INF, lrow0 = 0.f, lrow1 = 0.f;

    const int grp = lane >> 3, rw = lane & 7;
    const int c0  = (lane & 3) << 1;
    const int qr0 = wid * 16 + (lane >> 2);
    const int qr1 = qr0 + 8;

    for (int kt = 0; kt <= qt; kt++) {
        const int s = kt & 1;
        if (kt < qt) { load_stage(kt + 1, s ^ 1); CP_WAIT(1); }
        else         { CP_WAIT(0); }
        __syncthreads();

        if (kt == 0) {
            #pragma unroll
            for (int ks = 0; ks < 4; ks++) {
                const int row = wid * 16 + (grp & 1) * 8 + rw;
                const int ch  = 2 * ks + (grp >> 1);
                const uint32_t off = row * 128 + ((ch ^ (row & 7)) << 4);
                ldsm4(Qh[ks], sQh + off);
                ldsm4(Ql[ks], sQl + off);
            }
        }

        const uint32_t stK = stage_base + (uint32_t)s * 32768;
        const uint32_t stV = stK + 16384;

        float S[8][4];
        #pragma unroll
        for (int j = 0; j < 8; j++)
            #pragma unroll
            for (int e = 0; e < 4; e++) S[j][e] = 0.f;

        #pragma unroll
        for (int ks = 0; ks < 4; ks++) {
            uint32_t Bh[8][2], Bl[8][2];
            #pragma unroll
            for (int jp = 0; jp < 4; jp++) {
                const int row = jp * 16 + (grp >> 1) * 8 + rw;
                const int ch  = 2 * ks + (grp & 1);
                const uint32_t off = row * 128 + ((ch ^ (row & 7)) << 4);
                uint32_t t[4];
                ldsm4(t, stK + off);
                Bh[2*jp][0] = t[0]; Bh[2*jp][1] = t[1];
                Bh[2*jp+1][0] = t[2]; Bh[2*jp+1][1] = t[3];
                ldsm4(t, stK + 8192 + off);
                Bl[2*jp][0] = t[0]; Bl[2*jp][1] = t[1];
                Bl[2*jp+1][0] = t[2]; Bl[2*jp+1][1] = t[3];
            }
            #pragma unroll
            for (int j = 0; j < 8; j++) {
                mma_bf16(S[j], Qh[ks], Bh[j]);
                mma_bf16(S[j], Qh[ks], Bl[j]);
                mma_bf16(S[j], Ql[ks], Bh[j]);
            }
        }

        #pragma unroll
        for (int j = 0; j < 8; j++) {
            const int k0 = j * 8 + c0, k1 = k0 + 1;
            const float p0 = svp[kt * 64 + k0];
            const float p1 = svp[kt * 64 + k1];
            S[j][0] += p0; S[j][1] += p1; S[j][2] += p0; S[j][3] += p1;
            if (kt == qt) {
                if (k0 > qr0) S[j][0] = NEG_INF;
                if (k1 > qr0) S[j][1] = NEG_INF;
                if (k0 > qr1) S[j][2] = NEG_INF;
                if (k1 > qr1) S[j][3] = NEG_INF;
            }
        }
        float rm0 = NEG_INF, rm1 = NEG_INF;
        #pragma unroll
        for (int j = 0; j < 8; j++) {
            rm0 = fmaxf(rm0, fmaxf(S[j][0], S[j][1]));
            rm1 = fmaxf(rm1, fmaxf(S[j][2], S[j][3]));
        }
        rm0 = fmaxf(rm0, __shfl_xor_sync(0xffffffffu, rm0, 1));
        rm0 = fmaxf(rm0, __shfl_xor_sync(0xffffffffu, rm0, 2));
        rm1 = fmaxf(rm1, __shfl_xor_sync(0xffffffffu, rm1, 1));
        rm1 = fmaxf(rm1, __shfl_xor_sync(0xffffffffu, rm1, 2));

        const float mn0 = fmaxf(mrow0, rm0);
        const float mn1 = fmaxf(mrow1, rm1);
        const float al0 = (mrow0 == NEG_INF) ? 0.f : __expf(mrow0 - mn0);
        const float al1 = (mrow1 == NEG_INF) ? 0.f : __expf(mrow1 - mn1);

        float ps0 = 0.f, ps1 = 0.f;
        #pragma unroll
        for (int j = 0; j < 8; j++) {
            float p;
            p = (S[j][0] == NEG_INF) ? 0.f : __expf(S[j][0] - mn0); S[j][0] = p; ps0 += p;
            p = (S[j][1] == NEG_INF) ? 0.f : __expf(S[j][1] - mn0); S[j][1] = p; ps0 += p;
            p = (S[j][2] == NEG_INF) ? 0.f : __expf(S[j][2] - mn1); S[j][2] = p; ps1 += p;
            p = (S[j][3] == NEG_INF) ? 0.f : __expf(S[j][3] - mn1); S[j][3] = p; ps1 += p;
        }
        ps0 += __shfl_xor_sync(0xffffffffu, ps0, 1);
        ps0 += __shfl_xor_sync(0xffffffffu, ps0, 2);
        ps1 += __shfl_xor_sync(0xffffffffu, ps1, 1);
        ps1 += __shfl_xor_sync(0xffffffffu, ps1, 2);

        lrow0 = lrow0 * al0 + ps0; mrow0 = mn0;
        lrow1 = lrow1 * al1 + ps1; mrow1 = mn1;
        #pragma unroll
        for (int j = 0; j < 8; j++) {
            O[j][0] *= al0; O[j][1] *= al0;
            O[j][2] *= al1; O[j][3] *= al1;
        }

        #pragma unroll
        for (int ks = 0; ks < 4; ks++) {
            uint32_t Ph[4], Pl[4];
            splitpack(S[2*ks][0],   S[2*ks][1],   Ph[0], Pl[0]);
            splitpack(S[2*ks][2],   S[2*ks][3],   Ph[1], Pl[1]);
            splitpack(S[2*ks+1][0], S[2*ks+1][1], Ph[2], Pl[2]);
            splitpack(S[2*ks+1][2], S[2*ks+1][3], Ph[3], Pl[3]);

            uint32_t Vh[8][2], Vl[8][2];
            #pragma unroll
            for (int jp = 0; jp < 4; jp++) {
                const int row = ks * 16 + (grp & 1) * 8 + rw;
                const int ch  = 2 * jp + (grp >> 1);
                const uint32_t off = row * 128 + ((ch ^ (row & 7)) << 4);
                uint32_t t[4];
                ldsm4t(t, stV + off);
                Vh[2*jp][0] = t[0]; Vh[2*jp][1] = t[1];
                Vh[2*jp+1][0] = t[2]; Vh[2*jp+1][1] = t[3];
                ldsm4t(t, stV + 8192 + off);
                Vl[2*jp][0] = t[0]; Vl[2*jp][1] = t[1];
                Vl[2*jp+1][0] = t[2]; Vl[2*jp+1][1] = t[3];
            }
            #pragma unroll
            for (int j = 0; j < 8; j++) {
                mma_bf16(O[j], Ph, Vh[j]);
                mma_bf16(O[j], Ph, Vl[j]);
                mma_bf16(O[j], Pl, Vh[j]);
            }
        }
        __syncthreads();
    }

    const float ri0 = (lrow0 > 0.f) ? 1.f / lrow0 : 0.f;
    const float ri1 = (lrow1 > 0.f) ? 1.f / lrow1 : 0.f;
    const int m0 = b * 1024 + qt * 64 + qr0;
    const int m1 = m0 + 8;
    #pragma unroll
    for (int j = 0; j < 8; j++) {
        const int col = h * 64 + j * 8 + c0;
        const int chunk = col >> 5, wc = col & 31;
        uint32_t hi, lo;
        splitpack(O[j][0] * ri0, O[j][1] * ri0, hi, lo);
        size_t base = ((size_t)m0 * 32 + chunk) * 64 + wc;
        *(uint32_t*)(outp + base)      = hi;
        *(uint32_t*)(outp + base + 32) = lo;
        splitpack(O[j][2] * ri1, O[j][3] * ri1, hi, lo);
        base = ((size_t)m1 * 32 + chunk) * 64 + wc;
        *(uint32_t*)(outp + base)      = hi;
        *(uint32_t*)(outp + base + 32) = lo;
    }
}

// ---------------------------------------------------------------------------
extern "C" void kernel_launch(void* const* d_in, const int* in_sizes, int n_in,
                              void* d_out, int out_size)
{
    const float*     x   = (const float*)d_in[0];
    const long long* ids = (const long long*)d_in[1];
    const float*     Wq  = (const float*)d_in[2];
    const float*     bq  = (const float*)d_in[3];
    const float*     Wk  = (const float*)d_in[4];
    const float*     bk  = (const float*)d_in[5];
    const float*     Wv  = (const float*)d_in[6];
    const float*     bv  = (const float*)d_in[7];
    const float*     Wo  = (const float*)d_in[8];
    const float*     bo  = (const float*)d_in[9];
    float* out = (float*)d_out;

    __nv_bfloat16 *xc, *ac, *wqc, *wkc, *wvc, *woc;
    __nv_bfloat16 *qh, *ql, *kh, *kl, *vh, *vl;
    float* vb;
    cudaGetSymbolAddress((void**)&xc,  g_xc);
    cudaGetSymbolAddress((void**)&ac,  g_ac);
    cudaGetSymbolAddress((void**)&wqc, g_wqc);
    cudaGetSymbolAddress((void**)&wkc, g_wkc);
    cudaGetSymbolAddress((void**)&wvc, g_wvc);
    cudaGetSymbolAddress((void**)&woc, g_woc);
    cudaGetSymbolAddress((void**)&qh,  g_qh);
    cudaGetSymbolAddress((void**)&ql,  g_ql);
    cudaGetSymbolAddress((void**)&kh,  g_kh);
    cudaGetSymbolAddress((void**)&kl,  g_kl);
    cudaGetSymbolAddress((void**)&vh,  g_vh);
    cudaGetSymbolAddress((void**)&vl,  g_vl);
    cudaGetSymbolAddress((void**)&vb,  g_vb);

    const int gemm_smem  = 3 * 32768;             // 96KB -> 2 CTAs/SM
    const int flash_smem = 20480 + 2 * 32768;     // 86KB
    cudaFuncSetAttribute(gemm_qkv, cudaFuncAttributeMaxDynamicSharedMemorySize, gemm_smem);
    cudaFuncSetAttribute(gemm_ao,  cudaFuncAttributeMaxDynamicSharedMemorySize, gemm_smem);
    cudaFuncSetAttribute(flash_bf16, cudaFuncAttributeMaxDynamicSharedMemorySize, flash_smem);

    convert_split<<<(MROWS*128)/256, 256>>>(x,  xc,  MROWS);
    convert_split<<<(DD*128)/256,    256>>>(Wq, wqc, DD);
    convert_split<<<(DD*128)/256,    256>>>(Wk, wkc, DD);
    convert_split<<<(DD*128)/256,    256>>>(Wv, wvc, DD);
    convert_split<<<(DD*128)/256,    256>>>(Wo, woc, DD);
    pad_mask<<<MROWS/256, 256>>>(ids, vb);

    gemm_qkv<<<dim3(8, 64, 3), 256, gemm_smem>>>(xc, wqc, wkc, wvc, bq, bk, bv,
                                                 qh, ql, kh, kl, vh, vl);

    flash_bf16<<<dim3(16, 16, 8), 128, flash_smem>>>(qh, ql, kh, kl, vh, vl, vb, ac);

    gemm_ao<<<dim3(8, 64), 256, gemm_smem>>>(ac, woc, bo, out);
}